// round 6
// baseline (speedup 1.0000x reference)
#include <cuda_runtime.h>
#include <cuda_bf16.h>
#include <cstdint>

// ---------------------------------------------------------------------------
// GraphAutoencoder:
//   h   = x @ W_enc                                    [N, 128]
//   deg = in-degree(dst) + 1 (self loop); dinv = rsqrt(deg)
//   enc = sum_{e:(s->d)} h[s]*dinv[s]*dinv[d]  + h[i]*dinv[i]^2 + b_enc
//   out = sigmoid(enc @ W_dec + b_dec)                 [N, N]
// ---------------------------------------------------------------------------

#define N_NODES  10000
#define MAX_E    320000
#define IN_DIM   512
#define HID      128

// Scratch (device globals: no allocation allowed)
__device__ __align__(16) float g_h[N_NODES * HID];
__device__ __align__(16) float g_enc[N_NODES * HID];
__device__ float g_deg[N_NODES];
__device__ float g_dinv[N_NODES];
__device__ int   g_eidx[2 * MAX_E];   // canonical int32 edges: [0,E)=src, [E,2E)=dst
__device__ int   g_is64;

// ---------------------------------------------------------------------------
// 0a) Detect edge_index element width.
//     If the buffer really is int64, every 8-byte word is a node id < 10000.
//     If it is int32, an 8-byte word packs two random ids -> high half is
//     almost surely nonzero for at least one of 128 samples.
// ---------------------------------------------------------------------------
__global__ void detect_kernel(const void* __restrict__ e)
{
    const unsigned long long* p = (const unsigned long long*)e;
    int ok64 = 1;
    for (int i = 0; i < 128; ++i) {
        unsigned long long v = p[(size_t)i * 2499];   // max idx 317373 < 320000 words
        if (v >= (1ull << 31)) ok64 = 0;
    }
    g_is64 = ok64;
}

// 0b) Convert edges to canonical int32.
__global__ void convert_edges_kernel(const void* __restrict__ e, int E)
{
    int t = blockIdx.x * blockDim.x + threadIdx.x;
    if (t >= 2 * E) return;
    int v;
    if (g_is64) v = (int)((const long long*)e)[t];
    else        v = ((const int*)e)[t];
    g_eidx[t] = v;
}

// ---------------------------------------------------------------------------
// 1) Encoder GEMM: h = x @ W_enc   (M x 512) @ (512 x 128)
// ---------------------------------------------------------------------------
__global__ void encode_kernel(const float* __restrict__ x,
                              const float* __restrict__ W,
                              int M)
{
    int j   = threadIdx.x;                                   // 0..127
    int row = blockIdx.x * blockDim.y + threadIdx.y;
    if (row >= M) return;
    const float* xr = x + (size_t)row * IN_DIM;
    float acc = 0.0f;
#pragma unroll 8
    for (int k = 0; k < IN_DIM; ++k)
        acc = fmaf(__ldg(xr + k), __ldg(W + k * HID + j), acc);
    g_h[(size_t)row * HID + j] = acc;
}

// ---------------------------------------------------------------------------
// 2) Degree / normalization
// ---------------------------------------------------------------------------
__global__ void deg_init_kernel(int M)
{
    int i = blockIdx.x * blockDim.x + threadIdx.x;
    if (i < M) g_deg[i] = 1.0f;                              // self loop
}

__global__ void deg_count_kernel(int E)
{
    int t = blockIdx.x * blockDim.x + threadIdx.x;
    if (t >= E) return;
    int d = g_eidx[E + t];                                   // dst
    if (d >= 0 && d < N_NODES) atomicAdd(&g_deg[d], 1.0f);
}

__global__ void dinv_kernel(int M)
{
    int i = blockIdx.x * blockDim.x + threadIdx.x;
    if (i < M) g_dinv[i] = rsqrtf(g_deg[i]);
}

// ---------------------------------------------------------------------------
// 3) enc init: self-loop message + encoder bias
// ---------------------------------------------------------------------------
__global__ void enc_init_kernel(const float* __restrict__ b_enc, int M)
{
    int t = blockIdx.x * blockDim.x + threadIdx.x;
    if (t >= M * HID) return;
    int i = t >> 7;
    int j = t & (HID - 1);
    float di = g_dinv[i];
    g_enc[t] = g_h[t] * di * di + b_enc[j];
}

// ---------------------------------------------------------------------------
// 4) Edge scatter: one warp per edge, vector atomics (red.global.add.v4.f32)
//    h (5 MB) and enc (5 MB) are L2-resident.
// ---------------------------------------------------------------------------
__global__ void scatter_kernel(int E)
{
    int warp = (blockIdx.x * blockDim.x + threadIdx.x) >> 5;
    int lane = threadIdx.x & 31;
    if (warp >= E) return;
    int s = g_eidx[warp];            // src
    int d = g_eidx[E + warp];        // dst
    if ((unsigned)s >= N_NODES || (unsigned)d >= N_NODES) return;
    float norm = g_dinv[s] * g_dinv[d];
    float4 v = reinterpret_cast<const float4*>(g_h)[(size_t)s * (HID / 4) + lane];
    float* p = g_enc + (size_t)d * HID + lane * 4;
    asm volatile("red.global.add.v4.f32 [%0], {%1, %2, %3, %4};"
                 :: "l"(p), "f"(v.x * norm), "f"(v.y * norm),
                    "f"(v.z * norm), "f"(v.w * norm)
                 : "memory");
}

// ---------------------------------------------------------------------------
// 5) Decoder GEMM + bias + sigmoid:  out = sigmoid(enc @ W_dec + b_dec)
//    M=N=10000, K=128.  128x128 block tile, 8x8 per thread, BK=8.
//    Inner loop uses packed fma.rn.f32x2 (3-reg FFMA is half-rate on sm_103a).
// ---------------------------------------------------------------------------
#define BM 128
#define BN 128
#define BKD 8

__global__ __launch_bounds__(256)
void decode_kernel(const float* __restrict__ Wd,
                   const float* __restrict__ bd,
                   float* __restrict__ out,
                   int M, int N)
{
    __shared__ float As[BKD][BM];     // A transposed: As[k][m]
    __shared__ float Bs[BKD][BN];

    const int tid = threadIdx.x;
    const int m0  = blockIdx.y * BM;
    const int n0  = blockIdx.x * BN;

    const int aRow = tid >> 1;            // 0..127
    const int aCol = (tid & 1) * 4;       // 0 or 4
    const int bRow = tid >> 5;            // 0..7
    const int bCol = (tid & 31) * 4;      // 0..124

    const int tr = tid >> 4;              // 0..15 (row group)
    const int tc = tid & 15;              // 0..15 (col group)

    const bool fullN = (n0 + BN <= N);
    const bool aOK   = (m0 + aRow < M);

    unsigned long long acc[8][4];
#pragma unroll
    for (int i = 0; i < 8; ++i)
#pragma unroll
        for (int j = 0; j < 4; ++j) acc[i][j] = 0ull;

    for (int kk = 0; kk < HID; kk += BKD) {
        // --- stage A tile (transposed) ---
        float4 av = make_float4(0.f, 0.f, 0.f, 0.f);
        if (aOK)
            av = *reinterpret_cast<const float4*>(
                     &g_enc[(size_t)(m0 + aRow) * HID + kk + aCol]);
        As[aCol + 0][aRow] = av.x;
        As[aCol + 1][aRow] = av.y;
        As[aCol + 2][aRow] = av.z;
        As[aCol + 3][aRow] = av.w;

        // --- stage B tile ---
        if (fullN) {
            float4 bv = *reinterpret_cast<const float4*>(
                            &Wd[(size_t)(kk + bRow) * N + n0 + bCol]);
            *reinterpret_cast<float4*>(&Bs[bRow][bCol]) = bv;
        } else {
#pragma unroll
            for (int i = 0; i < 4; ++i) {
                int c = n0 + bCol + i;
                Bs[bRow][bCol + i] = (c < N)
                    ? Wd[(size_t)(kk + bRow) * N + c] : 0.f;
            }
        }
        __syncthreads();

#pragma unroll
        for (int k = 0; k < BKD; ++k) {
            float4 a0 = *reinterpret_cast<const float4*>(&As[k][tr * 8]);
            float4 a1 = *reinterpret_cast<const float4*>(&As[k][tr * 8 + 4]);
            float4 b0 = *reinterpret_cast<const float4*>(&Bs[k][tc * 8]);
            float4 b1 = *reinterpret_cast<const float4*>(&Bs[k][tc * 8 + 4]);

            unsigned long long bp[4];
            asm("mov.b64 %0, {%1, %2};" : "=l"(bp[0]) : "f"(b0.x), "f"(b0.y));
            asm("mov.b64 %0, {%1, %2};" : "=l"(bp[1]) : "f"(b0.z), "f"(b0.w));
            asm("mov.b64 %0, {%1, %2};" : "=l"(bp[2]) : "f"(b1.x), "f"(b1.y));
            asm("mov.b64 %0, {%1, %2};" : "=l"(bp[3]) : "f"(b1.z), "f"(b1.w));

            float a[8] = {a0.x, a0.y, a0.z, a0.w, a1.x, a1.y, a1.z, a1.w};
#pragma unroll
            for (int i = 0; i < 8; ++i) {
                unsigned long long ap;
                asm("mov.b64 %0, {%1, %2};" : "=l"(ap) : "f"(a[i]), "f"(a[i]));
#pragma unroll
                for (int j = 0; j < 4; ++j)
                    asm("fma.rn.f32x2 %0, %1, %2, %0;"
                        : "+l"(acc[i][j]) : "l"(ap), "l"(bp[j]));
            }
        }
        __syncthreads();
    }

    // --- epilogue: bias + sigmoid + store ---
    float bdv[8];
#pragma unroll
    for (int j = 0; j < 8; ++j) {
        int c = n0 + tc * 8 + j;
        bdv[j] = (c < N) ? bd[c] : 0.f;
    }

#pragma unroll
    for (int i = 0; i < 8; ++i) {
        int row = m0 + tr * 8 + i;
        if (row >= M) continue;
        float v[8];
#pragma unroll
        for (int j = 0; j < 4; ++j) {
            float lo, hi;
            asm("mov.b64 {%0, %1}, %2;" : "=f"(lo), "=f"(hi) : "l"(acc[i][j]));
            v[2 * j]     = lo;
            v[2 * j + 1] = hi;
        }
#pragma unroll
        for (int j = 0; j < 8; ++j) {
            float t = v[j] + bdv[j];
            v[j] = __fdividef(1.0f, 1.0f + __expf(-t));
        }
        size_t base = (size_t)row * N + n0 + tc * 8;
        if (fullN) {
            *reinterpret_cast<float4*>(&out[base]) =
                make_float4(v[0], v[1], v[2], v[3]);
            *reinterpret_cast<float4*>(&out[base + 4]) =
                make_float4(v[4], v[5], v[6], v[7]);
        } else {
#pragma unroll
            for (int j = 0; j < 8; ++j) {
                int c = n0 + tc * 8 + j;
                if (c < N) out[(size_t)row * N + c] = v[j];
            }
        }
    }
}

// ---------------------------------------------------------------------------
// Launch
// ---------------------------------------------------------------------------
extern "C" void kernel_launch(void* const* d_in, const int* in_sizes, int n_in,
                              void* d_out, int out_size)
{
    const float* x     = (const float*)d_in[0];
    const void*  ei    = d_in[1];
    const float* W_enc = (const float*)d_in[2];
    const float* b_enc = (const float*)d_in[3];
    const float* W_dec = (const float*)d_in[4];
    const float* b_dec = (const float*)d_in[5];
    float*       out   = (float*)d_out;

    const int M = in_sizes[5];        // N_NODES (10000)
    int E = in_sizes[1] / 2;          // 320000
    if (E > MAX_E) E = MAX_E;

    // 0) edge dtype detection + canonicalize to int32
    detect_kernel<<<1, 1>>>(ei);
    convert_edges_kernel<<<(2 * E + 255) / 256, 256>>>(ei, E);

    // 1) encoder GEMM
    {
        dim3 blk(HID, 4);
        int grid = (M + 3) / 4;
        encode_kernel<<<grid, blk>>>(x, W_enc, M);
    }
    // 2) degree + rsqrt
    deg_init_kernel <<<(M + 255) / 256, 256>>>(M);
    deg_count_kernel<<<(E + 255) / 256, 256>>>(E);
    dinv_kernel     <<<(M + 255) / 256, 256>>>(M);
    // 3) enc = self-loop + bias
    enc_init_kernel <<<(M * HID + 255) / 256, 256>>>(b_enc, M);
    // 4) edge scatter (one warp / edge)
    {
        int warps_per_blk = 256 / 32;
        int grid = (E + warps_per_blk - 1) / warps_per_blk;
        scatter_kernel<<<grid, 256>>>(E);
    }
    // 5) decoder GEMM + sigmoid
    {
        dim3 grid((M + BN - 1) / BN, (M + BM - 1) / BM);
        decode_kernel<<<grid, 256>>>(W_dec, b_dec, out, M, M);
    }
}